// round 10
// baseline (speedup 1.0000x reference)
#include <cuda_runtime.h>
#include <cuda_fp16.h>
#include <mma.h>
#include <cstdint>

#define NN 16384
#define DF 256
#define MT 128          // rows per CTA
#define BK 64           // K chunk
#define NCH (NN / BK)   // 256 chunks

// smem map (bytes)
#define SM_DEG 0                         // 128 ints (512 B)
#define SM_A   512                       // 128 x 72 halves = 18432 B (single buffer)
#define SM_B   (512 + 18432)             // 2 x (64 x 264 halves) = 67584 B
#define ASTR   72                        // A row stride (halves)
#define BSTR   264                       // B row stride (halves)
#define BBUF_BYTES (64 * BSTR * 2)       // 33792
#define SMEM_TOTAL (SM_B + 2 * BBUF_BYTES)   // 86528

__device__ __half g_xh[(size_t)NN * DF];    // x fp16 row-major
__device__ __half g_Wh[DF * DF];            // W fp16 row-major [out][in]
__device__ __half g_aggh[(size_t)NN * DF];  // mean-aggregated features fp16

// ---------------- prep kernels ----------------
__global__ void k_convX(const float* __restrict__ x) {
    const size_t i = (size_t)blockIdx.x * 256 + threadIdx.x;   // one float4 each
    const float4 v = ((const float4*)x)[i];
    __half2* d = (__half2*)(g_xh + i * 4);
    d[0] = __floats2half2_rn(v.x, v.y);
    d[1] = __floats2half2_rn(v.z, v.w);
}
__global__ void k_convW(const float* __restrict__ W) {
    const int i = blockIdx.x * 256 + threadIdx.x;
    g_Wh[i] = __float2half(W[i]);
}

// ---------------- main: agg = (A_tile @ x) / deg ----------------
__global__ void __launch_bounds__(512)
k_main(const int* __restrict__ adj) {
    using namespace nvcuda;
    extern __shared__ char smem[];
    int* degs = (int*)(smem + SM_DEG);
    __half* As = (__half*)(smem + SM_A);

    const int tid = threadIdx.x;
    const int w = tid >> 5, lid = tid & 31;
    const int blk = blockIdx.x;

    if (tid < 128) degs[tid] = 0;

    // A loader mapping: per chunk, thread handles 4 int4 (rows r0+32i, col group c4)
    const int r0 = tid >> 4, c4 = tid & 15;
    const int4* arow[4];
    int degl[4] = {0, 0, 0, 0};
#pragma unroll
    for (int i = 0; i < 4; ++i)
        arow[i] = (const int4*)(adj + (size_t)(blk * MT + r0 + 32 * i) * NN) + c4;

    // B loader mapping: 4 x 16B per chunk
    const int brow0 = tid >> 5, bcol = tid & 31;   // rows brow0+16i

    // warp tile: 32 rows x 64 cols
    const int wm = w >> 2, wn = w & 3;

    wmma::fragment<wmma::accumulator, 16, 16, 16, float> acc[2][4];
#pragma unroll
    for (int tm = 0; tm < 2; ++tm)
#pragma unroll
        for (int tn = 0; tn < 4; ++tn) wmma::fill_fragment(acc[tm][tn], 0.0f);

    __syncthreads();

    // prologue: B chunk 0 + A chunk 0 regs
    {
        const uint32_t bb = (uint32_t)__cvta_generic_to_shared(smem + SM_B);
#pragma unroll
        for (int i = 0; i < 4; ++i) {
            const __half* src = g_xh + (size_t)(brow0 + 16 * i) * DF + bcol * 8;
            asm volatile("cp.async.cg.shared.global [%0], [%1], 16;"
                         :: "r"(bb + (brow0 + 16 * i) * (BSTR * 2) + bcol * 16), "l"(src)
                         : "memory");
        }
        asm volatile("cp.async.commit_group;" ::: "memory");
    }
    int4 av[4];
#pragma unroll
    for (int i = 0; i < 4; ++i) av[i] = arow[i][0];

    for (int c = 0; c < NCH; ++c) {
        const int buf = c & 1;
        // convert + store A chunk c (from regs), accumulate degree
        const uint32_t ab = (uint32_t)__cvta_generic_to_shared(As);
#pragma unroll
        for (int i = 0; i < 4; ++i) {
            const int4 v = av[i];
            degl[i] += v.x + v.y + v.z + v.w;
            const uint32_t u0 = (uint32_t)v.x * 0x3C00u + (uint32_t)v.y * 0x3C000000u;
            const uint32_t u1 = (uint32_t)v.z * 0x3C00u + (uint32_t)v.w * 0x3C000000u;
            asm volatile("st.shared.v2.b32 [%0], {%1, %2};"
                         :: "r"(ab + (r0 + 32 * i) * (ASTR * 2) + c4 * 8),
                            "r"(u0), "r"(u1));
        }
        // B chunk c must have landed
        asm volatile("cp.async.wait_group 0;" ::: "memory");
        __syncthreads();

        // prefetch chunk c+1 (B async into other buffer, A into regs)
        if (c + 1 < NCH) {
            const int k0n = (c + 1) * BK;
            const uint32_t bb = (uint32_t)__cvta_generic_to_shared(smem + SM_B)
                                + (buf ^ 1) * BBUF_BYTES;
#pragma unroll
            for (int i = 0; i < 4; ++i) {
                const __half* src = g_xh + (size_t)(k0n + brow0 + 16 * i) * DF + bcol * 8;
                asm volatile("cp.async.cg.shared.global [%0], [%1], 16;"
                             :: "r"(bb + (brow0 + 16 * i) * (BSTR * 2) + bcol * 16), "l"(src)
                             : "memory");
            }
            asm volatile("cp.async.commit_group;" ::: "memory");
#pragma unroll
            for (int i = 0; i < 4; ++i) av[i] = arow[i][(c + 1) * 16];
        }

        // compute: acc += A_tile(32x64) @ B(64x64)
        const __half* Bs = (const __half*)(smem + SM_B + buf * BBUF_BYTES);
#pragma unroll
        for (int kk = 0; kk < 4; ++kk) {
            wmma::fragment<wmma::matrix_a, 16, 16, 16, half, wmma::row_major> a0, a1;
            wmma::load_matrix_sync(a0, As + (wm * 32 + 0) * ASTR + kk * 16, ASTR);
            wmma::load_matrix_sync(a1, As + (wm * 32 + 16) * ASTR + kk * 16, ASTR);
#pragma unroll
            for (int tn = 0; tn < 4; ++tn) {
                wmma::fragment<wmma::matrix_b, 16, 16, 16, half, wmma::row_major> b;
                wmma::load_matrix_sync(b, Bs + (kk * 16) * BSTR + wn * 64 + tn * 16, BSTR);
                wmma::mma_sync(acc[0][tn], a0, b, acc[0][tn]);
                wmma::mma_sync(acc[1][tn], a1, b, acc[1][tn]);
            }
        }
        __syncthreads();
    }

    // degree reduction
#pragma unroll
    for (int i = 0; i < 4; ++i) atomicAdd(&degs[r0 + 32 * i], degl[i]);
    __syncthreads();

    // epilogue: scale by 1/deg, write fp16 agg
    float* scratch = (float*)(smem + SM_A) + w * 256;   // 16x16 per warp
#pragma unroll
    for (int tm = 0; tm < 2; ++tm) {
#pragma unroll
        for (int tn = 0; tn < 4; ++tn) {
            wmma::store_matrix_sync(scratch, acc[tm][tn], 16, wmma::mem_row_major);
            __syncwarp();
            const int r = lid >> 1, ch = (lid & 1) * 8;
            const int lrow = wm * 32 + tm * 16 + r;
            const float inv = 1.0f / (float)degs[lrow];
            const float* s = scratch + r * 16 + ch;
            uint32_t pk[4];
#pragma unroll
            for (int j = 0; j < 4; ++j) {
                __half2 h = __floats2half2_rn(s[2 * j] * inv, s[2 * j + 1] * inv);
                pk[j] = *reinterpret_cast<uint32_t*>(&h);
            }
            *(uint4*)(g_aggh + (size_t)(blk * MT + lrow) * DF + wn * 64 + tn * 16 + ch) =
                make_uint4(pk[0], pk[1], pk[2], pk[3]);
            __syncwarp();
        }
    }
}

// ---------------- out = agg @ W^T + b ----------------
__global__ void k_out(const float* __restrict__ bias, float* __restrict__ out) {
    using namespace nvcuda;
    __shared__ float buf[8][16][16];
    const int w = threadIdx.x >> 5, lid = threadIdx.x & 31;
    const int cols = blockIdx.x * 16;
    const int rows = (blockIdx.y * 8 + w) * 16;

    wmma::fragment<wmma::accumulator, 16, 16, 16, float> c;
    wmma::fill_fragment(c, 0.0f);
#pragma unroll
    for (int k = 0; k < 16; ++k) {
        wmma::fragment<wmma::matrix_a, 16, 16, 16, half, wmma::row_major> a;
        wmma::fragment<wmma::matrix_b, 16, 16, 16, half, wmma::col_major> b;
        wmma::load_matrix_sync(a, g_aggh + (size_t)rows * DF + k * 16, DF);
        wmma::load_matrix_sync(b, g_Wh + (size_t)cols * DF + k * 16, DF);
        wmma::mma_sync(c, a, b, c);
    }
    wmma::store_matrix_sync(&buf[w][0][0], c, 16, wmma::mem_row_major);
    __syncwarp();
#pragma unroll
    for (int i = 0; i < 8; ++i) {
        const int e = i * 32 + lid;
        const int r = e >> 4, cc = e & 15;
        out[(size_t)(rows + r) * DF + cols + cc] = buf[w][r][cc] + bias[cols + cc];
    }
}

extern "C" void kernel_launch(void* const* d_in, const int* in_sizes, int n_in,
                              void* d_out, int out_size) {
    const float* x    = (const float*)d_in[0];
    const int*   adj  = (const int*)d_in[1];
    const float* W    = (const float*)d_in[2];
    const float* bias = (const float*)d_in[3];
    float* out = (float*)d_out;

    cudaFuncSetAttribute((const void*)k_main,
                         cudaFuncAttributeMaxDynamicSharedMemorySize, SMEM_TOTAL);

    k_convX<<<(NN * DF / 4) / 256, 256>>>(x);
    k_convW<<<DF * DF / 256, 256>>>(W);
    k_main<<<NN / MT, 512, SMEM_TOTAL>>>(adj);
    k_out<<<dim3(DF / 16, NN / 128), 256>>>(bias, out);
}